// round 17
// baseline (speedup 1.0000x reference)
#include <cuda_runtime.h>
#include <cuda_fp16.h>
#include <cstdint>
#include <cmath>

#define B_ 64
#define S_ 512
#define D_ 1024
#define H_ 1024
#define G_ 4096
#define RBLK 128

// ---------------- scratch (device globals) ----------------
__device__ __half g_xh[(size_t)B_ * S_ * D_];   // x fp16 [b][s][d]
__device__ __half g_Wh[(size_t)G_ * D_];        // W^T perm [n'][k] fp16
__device__ __half g_Uh[(size_t)G_ * H_];        // U^T perm [n'][k] fp16
__device__ __half g_hh[2][B_ * H_];             // h fp16 [b][j], dbl buf
__device__ unsigned g_flag[RBLK * 16];          // per-CTA monotonic step flags

// ---------------- helpers ----------------
__device__ __forceinline__ uint32_t smem_u32(const void* p) {
    uint32_t a;
    asm("{ .reg .u64 t; cvta.to.shared.u64 t, %1; cvt.u32.u64 %0, t; }" : "=r"(a) : "l"(p));
    return a;
}
__device__ __forceinline__ void ldm_x4(uint32_t* r, uint32_t a) {
    asm volatile("ldmatrix.sync.aligned.m8n8.x4.shared.b16 {%0,%1,%2,%3}, [%4];"
                 : "=r"(r[0]), "=r"(r[1]), "=r"(r[2]), "=r"(r[3]) : "r"(a));
}
__device__ __forceinline__ void mma16816(float* d, const uint32_t* a, const uint32_t* b) {
    asm volatile("mma.sync.aligned.m16n8k16.row.col.f32.f16.f16.f32 "
                 "{%0,%1,%2,%3},{%4,%5,%6,%7},{%8,%9},{%0,%1,%2,%3};"
                 : "+f"(d[0]), "+f"(d[1]), "+f"(d[2]), "+f"(d[3])
                 : "r"(a[0]), "r"(a[1]), "r"(a[2]), "r"(a[3]), "r"(b[0]), "r"(b[1]));
}
__device__ __forceinline__ void cpa16(uint32_t dst, const void* src) {
    asm volatile("cp.async.cg.shared.global [%0], [%1], 16;" :: "r"(dst), "l"(src));
}
#define CP_COMMIT() asm volatile("cp.async.commit_group;" ::: "memory")
#define CP_WAITN(n) asm volatile("cp.async.wait_group %0;" :: "n"(n) : "memory")
#define BAR_C() asm volatile("bar.sync 1, 256;" ::: "memory")
#define BAR_P() asm volatile("bar.sync 2, 128;" ::: "memory")
__device__ __forceinline__ float fsig(float x) {
    return __fdividef(1.f, 1.f + __expf(-x));
}
__device__ __forceinline__ float ftanh(float x) {
    x = fminf(fmaxf(x, -15.f), 15.f);
    float e = __expf(2.f * x);
    return __fdividef(e - 1.f, e + 1.f);
}

// ---------------- x: fp32 -> fp16 ----------------
__global__ void split_x(const float* __restrict__ x) {
    size_t i = ((size_t)blockIdx.x * 256 + threadIdx.x) * 8;
    float4 v0 = *(const float4*)(x + i);
    float4 v1 = *(const float4*)(x + i + 4);
    __half h[8] = {__float2half(v0.x), __float2half(v0.y), __float2half(v0.z), __float2half(v0.w),
                   __float2half(v1.x), __float2half(v1.y), __float2half(v1.z), __float2half(v1.w)};
    *(uint4*)(g_xh + i) = *(uint4*)h;
}

// ---------------- W/U prep (merged) + global flag init ----------------
__global__ void prep_wu(const float* __restrict__ W, const float* __restrict__ U) {
    __shared__ float tile[32][33];
    const float* in = blockIdx.z ? U : W;
    __half* oh = blockIdx.z ? g_Uh : g_Wh;
    int n0 = blockIdx.x * 32, k0 = blockIdx.y * 32;
    int tx = threadIdx.x, ty = threadIdx.y;
#pragma unroll
    for (int i = 0; i < 4; i++)
        tile[ty + i * 8][tx] = in[(size_t)(k0 + ty + i * 8) * G_ + n0 + tx];
    __syncthreads();
#pragma unroll
    for (int i = 0; i < 4; i++) {
        int n = n0 + ty + i * 8;
        int gate = n >> 10, j = n & 1023;
        int np = ((j >> 3) << 5) + (gate << 3) + (j & 7);
        oh[(size_t)np * 1024 + k0 + tx] = __float2half(tile[tx][ty + i * 8]);
    }
    if (blockIdx.x == 0 && blockIdx.y == 0 && blockIdx.z == 0) {
        int tid = ty * 32 + tx;
        for (int i = tid; i < RBLK * 16; i += 256) g_flag[i] = 0;
    }
}

// ---------------- warp-specialized persistent LSTM ----------------
// Warps 0-7 (256 thr): recurrence consumer (R11 structure, named bars).
// Warps 8-11 (128 thr): xW producer -> smem ring (fp16, 2 slots).
// smem: U[32][2064] | W[32][2064] | H[2][64][272] | X[2][64][144] |
//       ring[2][32*64 fp16] | Gk0 | Gk1 | bias[32] | flags
#define UPB 2064
#define HPB 272
#define XPB 144
#define WOFF 66048
#define HOFF 132096
#define HCB 17408
#define XOFF 166912
#define XCB 9216
#define RINGO 185344
#define GS0O 193536
#define GS1O 201984
#define BIASO 210432
#define FLAGO 210560
#define RSM 210688

__global__ __launch_bounds__(384, 1) void lstm_recur(float* __restrict__ out,
                                                     float* __restrict__ hT,
                                                     float* __restrict__ cT,
                                                     const float* __restrict__ bias) {
    extern __shared__ char sm[];
    uint32_t sb = smem_u32(sm);
    int tid = threadIdx.x, lane = tid & 31;
    int jt = blockIdx.x, n0r = jt * 32, j0 = jt * 8;

    // ---- cooperative init: U + W resident tiles (data granules only) ----
    for (int i = tid; i < 8192; i += 384) {
        int which = i >> 12;                 // 0 = U, 1 = W
        int g = i & 4095;
        int row = g >> 7, col = g & 127;     // 128 granules (16B) per 2048B row
        const __half* src = (which ? g_Wh : g_Uh) + (size_t)(n0r + row) * 1024 + col * 8;
        char* dst = sm + (which ? WOFF : 0) + row * UPB + col * 16;
        *(uint4*)dst = *(const uint4*)src;
    }
    if (tid < 32) {
        int np = n0r + tid;
        int gate = (np >> 3) & 3;
        int jo = ((np >> 5) << 3) + (np & 7);
        ((float*)(sm + BIASO))[tid] = bias[gate * H_ + jo];
    }
    volatile int* xwflag = (volatile int*)(sm + FLAGO);      // [2]
    volatile int* xwdone = (volatile int*)(sm + FLAGO + 8);
    if (tid < 3) ((int*)(sm + FLAGO))[tid] = 0;
    asm volatile("bar.sync 0;" ::: "memory");                // full-CTA once

    if (tid < 256) {
        // ================= CONSUMER: recurrence =================
        int w = tid >> 5;
        int wm = w & 1, wn = (w >> 1) & 1, kg = w >> 2;      // 2m x 2n x 2kg
        uint32_t aoff = (uint32_t)((wm * 32 + (lane & 15)) * HPB + (lane >> 4) * 16 + kg * 128);
        uint32_t boff = (uint32_t)((wn * 16 + (lane & 15)) * UPB + (lane >> 4) * 16 + kg * 128);
        float* Gk = (float*)(sm + GS0O + kg * 8448);
        float* Gs0 = (float*)(sm + GS0O);
        float* Gs1 = (float*)(sm + GS1O);
        float* bias_s = (float*)(sm + BIASO);
        int hrow = tid >> 2, hseg = tid & 3;                 // h staging: 4 thr/row
        int eb = tid & 63, jj0 = (tid >> 6) * 2;
        float creg0 = 0.f, creg1 = 0.f;
        const unsigned* myflag = &g_flag[(tid & 127) * 16];

        for (int t = 0; t < S_; t++) {
            float acc[2][2][4];
#pragma unroll
            for (int i = 0; i < 2; i++)
#pragma unroll
                for (int j = 0; j < 2; j++)
#pragma unroll
                    for (int q = 0; q < 4; q++) acc[i][j][q] = 0.f;

            if (t > 0) {
                if (tid < RBLK) {            // dataflow wait for h(t) producers
                    unsigned v;
                    do {
                        asm volatile("ld.global.acquire.gpu.u32 %0, [%1];" : "=r"(v) : "l"(myflag) : "memory");
                        if (v < (unsigned)t) __nanosleep(32);
                    } while (v < (unsigned)t);
                }
                BAR_C();
                const __half* hh = g_hh[t & 1];
                auto issue_h = [&](int c) {
                    const __half* s = hh + (size_t)hrow * H_ + c * 128 + hseg * 32;
                    uint32_t d = sb + HOFF + (uint32_t)(c & 1) * HCB
                               + (uint32_t)(hrow * HPB + hseg * 64);
                    cpa16(d, s); cpa16(d + 16, s + 8);
                    cpa16(d + 32, s + 16); cpa16(d + 48, s + 24);
                    CP_COMMIT();
                };
                issue_h(0);
                issue_h(1);
                for (int c = 0; c < 8; c++) {
                    if (c < 7) { CP_WAITN(1); } else { CP_WAITN(0); }
                    BAR_C();
                    uint32_t AH = sb + HOFF + (uint32_t)(c & 1) * HCB;
                    uint32_t BH = sb + (uint32_t)c * 256;     // U tile at 0
#pragma unroll
                    for (int kk = 0; kk < 4; kk++) {
                        uint32_t kb = (uint32_t)kk * 32;
                        uint32_t a0[4], a1[4], tb[4], b0[2], b1[2];
                        ldm_x4(a0, AH + aoff + kb);
                        ldm_x4(a1, AH + aoff + 16 * HPB + kb);
                        ldm_x4(tb, BH + boff + kb);
                        b0[0] = tb[0]; b0[1] = tb[2];
                        b1[0] = tb[1]; b1[1] = tb[3];
                        mma16816(acc[0][0], a0, b0);
                        mma16816(acc[0][1], a0, b1);
                        mma16816(acc[1][0], a1, b0);
                        mma16816(acc[1][1], a1, b1);
                    }
                    if (c < 6) {
                        BAR_C();             // all warps done with buf (c&1)
                        issue_h(c + 2);
                    }
                }
            }
            // stage split-kg partial gates (R11 layout)
            {
                int rb = wm * 32 + (lane >> 2);
                int cb = wn * 16 + (lane & 3) * 2;
#pragma unroll
                for (int mt = 0; mt < 2; mt++)
#pragma unroll
                    for (int nt = 0; nt < 2; nt++) {
                        int rr2 = rb + mt * 16, cc2 = cb + nt * 8;
                        Gk[rr2 * 33 + cc2]           = acc[mt][nt][0];
                        Gk[rr2 * 33 + cc2 + 1]       = acc[mt][nt][1];
                        Gk[(rr2 + 8) * 33 + cc2]     = acc[mt][nt][2];
                        Gk[(rr2 + 8) * 33 + cc2 + 1] = acc[mt][nt][3];
                    }
            }
            BAR_C();
            // wait for producer's xw tile for this t (smem ring)
            {
                volatile int* f = &xwflag[t & 1];
                while (*f < t + 1) __nanosleep(32);
            }
            // fused cell update
            {
                const __half* xwr = (const __half*)(sm + RINGO + (size_t)(t & 1) * 4096);
                float hv0, hv1;
#pragma unroll
                for (int u = 0; u < 2; u++) {
                    int jj = jj0 + u;
                    float vi = Gs0[eb * 33 + jj]      + Gs1[eb * 33 + jj]
                             + __half2float(xwr[jj * 64 + eb])        + bias_s[jj];
                    float vf = Gs0[eb * 33 + 8 + jj]  + Gs1[eb * 33 + 8 + jj]
                             + __half2float(xwr[(8 + jj) * 64 + eb])  + bias_s[8 + jj];
                    float vg = Gs0[eb * 33 + 16 + jj] + Gs1[eb * 33 + 16 + jj]
                             + __half2float(xwr[(16 + jj) * 64 + eb]) + bias_s[16 + jj];
                    float vo = Gs0[eb * 33 + 24 + jj] + Gs1[eb * 33 + 24 + jj]
                             + __half2float(xwr[(24 + jj) * 64 + eb]) + bias_s[24 + jj];
                    float& cr = u ? creg1 : creg0;
                    cr = fsig(vf) * cr + fsig(vi) * ftanh(vg);
                    float hv = fsig(vo) * ftanh(cr);
                    if (u) hv1 = hv; else hv0 = hv;
                }
                __half hb2[2] = {__float2half(hv0), __float2half(hv1)};
                *(uint32_t*)&g_hh[(t + 1) & 1][eb * H_ + j0 + jj0] = *(uint32_t*)hb2;
                float* op = out + (size_t)eb * ((size_t)S_ * H_) + (size_t)t * H_ + j0 + jj0;
                *(float2*)op = make_float2(hv0, hv1);
                if (t == S_ - 1 && cT != nullptr) {
                    *(float2*)&hT[eb * H_ + j0 + jj0] = make_float2(hv0, hv1);
                    *(float2*)&cT[eb * H_ + j0 + jj0] = make_float2(creg0, creg1);
                }
            }
            BAR_C();
            if (tid == 0) {
                if (t < S_ - 1) {
                    __threadfence();
                    asm volatile("st.global.relaxed.gpu.u32 [%0], %1;"
                                 :: "l"(&g_flag[jt * 16]), "r"((unsigned)(t + 1)) : "memory");
                }
                __threadfence_block();
                xwdone[0] = t + 1;           // ring slot (t) fully consumed
            }
        }
    } else {
        // ================= PRODUCER: xW tiles -> smem ring =================
        int ptid = tid - 256;
        int p = ptid >> 5;                   // producer warp 0..3, rows b = p*16..
        uint32_t aoffP = (uint32_t)((p * 16 + (lane & 15)) * XPB + (lane >> 4) * 16);
        uint32_t bP0 = (uint32_t)WOFF + (uint32_t)((lane & 15) * UPB + (lane >> 4) * 16);
        uint32_t bP1 = bP0 + 16 * UPB;
        int xrow = ptid >> 1, xseg = ptid & 1;   // x staging: 2 thr/row

        for (int t = 0; t < S_; t++) {
            if (t >= 2) {                    // ring slot reuse: consumer done with t-2
                while (xwdone[0] < t - 1) __nanosleep(32);
            }
            auto issue_x = [&](int c) {
                const __half* s = g_xh + ((size_t)xrow * S_ + t) * D_ + c * 64 + xseg * 32;
                uint32_t d = sb + XOFF + (uint32_t)(c & 1) * XCB
                           + (uint32_t)(xrow * XPB + xseg * 64);
                cpa16(d, s); cpa16(d + 16, s + 8);
                cpa16(d + 32, s + 16); cpa16(d + 48, s + 24);
                CP_COMMIT();
            };
            issue_x(0);
            issue_x(1);
            float accp[4][4];
#pragma unroll
            for (int i = 0; i < 4; i++)
#pragma unroll
                for (int q = 0; q < 4; q++) accp[i][q] = 0.f;

            for (int c = 0; c < 16; c++) {
                if (c < 15) { CP_WAITN(1); } else { CP_WAITN(0); }
                BAR_P();
                uint32_t XA = sb + XOFF + (uint32_t)(c & 1) * XCB;
                uint32_t wb = (uint32_t)c * 128;
#pragma unroll
                for (int kk = 0; kk < 4; kk++) {
                    uint32_t kb = (uint32_t)kk * 32;
                    uint32_t a[4], tl[4], th[4], b0[2], b1[2], b2[2], b3[2];
                    ldm_x4(a, XA + aoffP + kb);
                    ldm_x4(tl, sb + bP0 + wb + kb);
                    ldm_x4(th, sb + bP1 + wb + kb);
                    b0[0] = tl[0]; b0[1] = tl[2];
                    b1[0] = tl[1]; b1[1] = tl[3];
                    b2[0] = th[0]; b2[1] = th[2];
                    b3[0] = th[1]; b3[1] = th[3];
                    mma16816(accp[0], a, b0);
                    mma16816(accp[1], a, b1);
                    mma16816(accp[2], a, b2);
                    mma16816(accp[3], a, b3);
                }
                if (c < 14) {
                    BAR_P();
                    issue_x(c + 2);
                }
            }
            // store tile to ring slot (layout [n'_rel][b] fp16)
            {
                __half* ring = (__half*)(sm + RINGO + (size_t)(t & 1) * 4096);
                int r = p * 16 + (lane >> 2);
                int cb = (lane & 3) * 2;
#pragma unroll
                for (int nt = 0; nt < 4; nt++) {
                    int cc = nt * 8 + cb;
                    ring[cc * 64 + r]           = __float2half(accp[nt][0]);
                    ring[(cc + 1) * 64 + r]     = __float2half(accp[nt][1]);
                    ring[cc * 64 + r + 8]       = __float2half(accp[nt][2]);
                    ring[(cc + 1) * 64 + r + 8] = __float2half(accp[nt][3]);
                }
            }
            BAR_P();
            if (ptid == 0) {
                __threadfence_block();
                xwflag[t & 1] = t + 1;
            }
        }
    }
}

// ---------------- launch ----------------
extern "C" void kernel_launch(void* const* d_in, const int* in_sizes, int n_in,
                              void* d_out, int out_size) {
    const float* x    = (const float*)d_in[0];
    const float* W    = (const float*)d_in[1];
    const float* U    = (const float*)d_in[2];
    const float* bias = (const float*)d_in[3];
    float* out = (float*)d_out;

    float* hT = nullptr;
    float* cT = nullptr;
    long long need = (long long)B_ * S_ * H_ + 2LL * B_ * H_;
    if ((long long)out_size >= need) {
        hT = out + (size_t)B_ * S_ * H_;
        cT = hT + (size_t)B_ * H_;
    }

    cudaFuncSetAttribute(lstm_recur, cudaFuncAttributeMaxDynamicSharedMemorySize, RSM);

    split_x<<<(B_ * S_ * D_) / (256 * 8), 256>>>(x);
    prep_wu<<<dim3(128, 32, 2), dim3(32, 8)>>>(W, U);
    lstm_recur<<<RBLK, 384, RSM>>>(out, hT, cT, bias);
}